// round 1
// baseline (speedup 1.0000x reference)
#include <cuda_runtime.h>
#include <cuda_bf16.h>

// Problem: labels [16, 8, 512, 512] f32  ->  scalar f32
//   opened = grey_opening(labels, size=2)   (2x2 min then 2x2 max, symmetric pad)
//   out    = mean((labels - opened)^2)
//
// size=2 semantics (derived from the reference):
//   erosion : e[i] = min(x[i-1], x[i])   (i-1 clamped to 0)
//   dilation: o[i] = max(e[i], e[i+1])   (i+1 clamped to H-1)
// separable in 2D.

#define IMG_H   512
#define IMG_W   512
#define N_IMG   128          // 16 * 8
#define STRIP   32           // output rows per thread
#define N_STRIP (IMG_H / STRIP)   // 16
#define CGRP    (IMG_W / 8)       // 64 column-groups of 8
#define TPB     256
#define N_BLK   ((N_IMG * N_STRIP * CGRP) / TPB)   // 512
#define TOTAL_ELEMS 33554432.0

__device__ double g_partials[N_BLK];

// Load 10 consecutive columns (c0-1 .. c0+8) of row rr, with symmetric clamp
// at the image's left/right edge. c0 is a multiple of 8 -> float4 aligned.
__device__ __forceinline__ void load_row(const float* __restrict__ base, int rr,
                                         int c0, float v[10]) {
    const float* p = base + rr * IMG_W + c0;
    float4 a = __ldg(reinterpret_cast<const float4*>(p));
    float4 b = __ldg(reinterpret_cast<const float4*>(p + 4));
    v[1] = a.x; v[2] = a.y; v[3] = a.z; v[4] = a.w;
    v[5] = b.x; v[6] = b.y; v[7] = b.z; v[8] = b.w;
    v[0] = (c0 == 0)           ? a.x : __ldg(p - 1);   // erosion left pad: dup col 0
    v[9] = (c0 + 8 == IMG_W)   ? b.w : __ldg(p + 8);   // placeholder at right edge
}

__global__ void __launch_bounds__(TPB)
opening_mse_kernel(const float* __restrict__ x) {
    const int t     = blockIdx.x * TPB + threadIdx.x;
    const int img   = t >> 10;            // 16 strips * 64 cgroups = 1024 threads/img
    const int rem   = t & 1023;
    const int strip = rem >> 6;
    const int cg    = rem & 63;
    const int c0    = cg << 3;
    const int rs    = strip * STRIP;
    const bool right_edge = (c0 + 8 == IMG_W);

    const float* __restrict__ base = x + (size_t)img * (IMG_H * IMG_W);

    // rowmin of the row ABOVE the strip (row rs-1; clamped -> row rs when rs==0,
    // which is exactly the erosion top pad: e[0] = rowmin[0]).
    float rm_prev[9];
    {
        float v[10];
        load_row(base, (rs > 0) ? rs - 1 : 0, c0, v);
        #pragma unroll
        for (int k = 0; k < 9; k++) rm_prev[k] = fminf(v[k], v[k + 1]);
        if (right_edge) rm_prev[8] = rm_prev[7];  // dilation right pad: dup eroded col 511
    }

    float hprev[8], xbuf[8];
    #pragma unroll
    for (int k = 0; k < 8; k++) { hprev[k] = 0.f; xbuf[k] = 0.f; }
    float acc = 0.f;

    // Pipeline down the rows. At input row r we produce opened row r-1.
    #pragma unroll 4
    for (int i = 0; i < STRIP; i++) {
        float v[10];
        load_row(base, rs + i, c0, v);

        float rm[9], er[9];
        #pragma unroll
        for (int k = 0; k < 9; k++) rm[k] = fminf(v[k], v[k + 1]);
        if (right_edge) rm[8] = rm[7];            // clamp eroded at col 512 -> col 511
        #pragma unroll
        for (int k = 0; k < 9; k++) { er[k] = fminf(rm_prev[k], rm[k]); rm_prev[k] = rm[k]; }

        float h[8];
        #pragma unroll
        for (int k = 0; k < 8; k++) h[k] = fmaxf(er[k], er[k + 1]);

        if (i > 0) {
            #pragma unroll
            for (int k = 0; k < 8; k++) {
                float o = fmaxf(hprev[k], h[k]);  // opened at row rs+i-1
                float d = xbuf[k] - o;
                acc = fmaf(d, d, acc);
            }
        }
        #pragma unroll
        for (int k = 0; k < 8; k++) { hprev[k] = h[k]; xbuf[k] = v[k + 1]; }
    }

    // Finish output row rs+STRIP-1: needs hmax of row rs+STRIP (or bottom clamp).
    if (rs + STRIP < IMG_H) {
        float v[10];
        load_row(base, rs + STRIP, c0, v);
        float rm[9], er[9];
        #pragma unroll
        for (int k = 0; k < 9; k++) rm[k] = fminf(v[k], v[k + 1]);
        if (right_edge) rm[8] = rm[7];
        #pragma unroll
        for (int k = 0; k < 9; k++) er[k] = fminf(rm_prev[k], rm[k]);
        float h[8];
        #pragma unroll
        for (int k = 0; k < 8; k++) h[k] = fmaxf(er[k], er[k + 1]);
        #pragma unroll
        for (int k = 0; k < 8; k++) {
            float o = fmaxf(hprev[k], h[k]);
            float d = xbuf[k] - o;
            acc = fmaf(d, d, acc);
        }
    } else {
        // bottom row: dilation pad duplicates eroded row 511 -> opened = hprev
        #pragma unroll
        for (int k = 0; k < 8; k++) {
            float d = xbuf[k] - hprev[k];
            acc = fmaf(d, d, acc);
        }
    }

    // ---- block reduction (deterministic: no float atomics) ----
    #pragma unroll
    for (int off = 16; off > 0; off >>= 1)
        acc += __shfl_down_sync(0xffffffffu, acc, off);

    __shared__ float ws[TPB / 32];
    if ((threadIdx.x & 31) == 0) ws[threadIdx.x >> 5] = acc;
    __syncthreads();
    if (threadIdx.x == 0) {
        float s = 0.f;
        #pragma unroll
        for (int w = 0; w < TPB / 32; w++) s += ws[w];
        g_partials[blockIdx.x] = (double)s;
    }
}

__global__ void __launch_bounds__(N_BLK)
finalize_kernel(float* __restrict__ out) {
    __shared__ double sh[N_BLK];
    sh[threadIdx.x] = g_partials[threadIdx.x];
    __syncthreads();
    #pragma unroll
    for (int s = N_BLK / 2; s > 0; s >>= 1) {
        if (threadIdx.x < s) sh[threadIdx.x] += sh[threadIdx.x + s];
        __syncthreads();
    }
    if (threadIdx.x == 0) out[0] = (float)(sh[0] / TOTAL_ELEMS);
}

extern "C" void kernel_launch(void* const* d_in, const int* in_sizes, int n_in,
                              void* d_out, int out_size) {
    (void)in_sizes; (void)n_in; (void)out_size;
    const float* labels = (const float*)d_in[0];
    float* out = (float*)d_out;
    opening_mse_kernel<<<N_BLK, TPB>>>(labels);
    finalize_kernel<<<1, N_BLK>>>(out);
}

// round 3
// speedup vs baseline: 1.0737x; 1.0737x over previous
#include <cuda_runtime.h>
#include <cuda_bf16.h>

// Problem: labels [16, 8, 512, 512] f32  ->  scalar f32
//   opened = grey_opening(labels, size=2)   (2x2 min then 2x2 max, symmetric pad)
//   out    = mean((labels - opened)^2)
//
// size=2 semantics (derived from the reference):
//   erosion : e[i] = min(x[i-1], x[i])   (i-1 clamped to 0)
//   dilation: o[i] = max(e[i], e[i+1])   (i+1 clamped to H-1)
// separable in 2D. Single fused kernel: stencil + MSE + last-block reduction.

#define IMG_H   512
#define IMG_W   512
#define N_IMG   128          // 16 * 8
#define STRIP   32           // output rows per thread
#define N_STRIP (IMG_H / STRIP)   // 16
#define CGRP    (IMG_W / 8)       // 64 column-groups of 8
#define TPB     256
#define N_BLK   ((N_IMG * N_STRIP * CGRP) / TPB)   // 512
#define TOTAL_ELEMS 33554432.0

__device__ double       g_partials[N_BLK];
__device__ unsigned int g_tickets = 0;   // reset by last block each call -> replay-safe

// Load 10 consecutive columns (c0-1 .. c0+8) of row rr, with symmetric clamp
// at the image's left/right edge. c0 is a multiple of 8 -> float4 aligned.
__device__ __forceinline__ void load_row(const float* __restrict__ base, int rr,
                                         int c0, float v[10]) {
    const float* p = base + rr * IMG_W + c0;
    float4 a = __ldg(reinterpret_cast<const float4*>(p));
    float4 b = __ldg(reinterpret_cast<const float4*>(p + 4));
    v[1] = a.x; v[2] = a.y; v[3] = a.z; v[4] = a.w;
    v[5] = b.x; v[6] = b.y; v[7] = b.z; v[8] = b.w;
    v[0] = (c0 == 0)         ? a.x : __ldg(p - 1);   // erosion left pad: dup col 0
    v[9] = (c0 + 8 == IMG_W) ? b.w : __ldg(p + 8);   // placeholder at right edge
}

__global__ void __launch_bounds__(TPB)
opening_mse_kernel(const float* __restrict__ x, float* __restrict__ out) {
    const int t     = blockIdx.x * TPB + threadIdx.x;
    const int img   = t >> 10;            // 16 strips * 64 cgroups = 1024 threads/img
    const int rem   = t & 1023;
    const int strip = rem >> 6;
    const int cg    = rem & 63;
    const int c0    = cg << 3;
    const int rs    = strip * STRIP;
    const bool right_edge = (c0 + 8 == IMG_W);

    const float* __restrict__ base = x + (size_t)img * (IMG_H * IMG_W);

    // rowmin of the row ABOVE the strip (row rs-1; clamped -> row rs when rs==0,
    // which is exactly the erosion top pad: e[0] = rowmin[0]).
    float rm_prev[9];
    {
        float v[10];
        load_row(base, (rs > 0) ? rs - 1 : 0, c0, v);
        #pragma unroll
        for (int k = 0; k < 9; k++) rm_prev[k] = fminf(v[k], v[k + 1]);
        if (right_edge) rm_prev[8] = rm_prev[7];  // dilation right pad: dup eroded col 511
    }

    float hprev[8], xbuf[8];
    #pragma unroll
    for (int k = 0; k < 8; k++) { hprev[k] = 0.f; xbuf[k] = 0.f; }
    float acc = 0.f;

    // Pipeline down the rows. At input row r we produce opened row r-1.
    #pragma unroll 4
    for (int i = 0; i < STRIP; i++) {
        float v[10];
        load_row(base, rs + i, c0, v);

        float rm[9], er[9];
        #pragma unroll
        for (int k = 0; k < 9; k++) rm[k] = fminf(v[k], v[k + 1]);
        if (right_edge) rm[8] = rm[7];            // clamp eroded at col 512 -> col 511
        #pragma unroll
        for (int k = 0; k < 9; k++) { er[k] = fminf(rm_prev[k], rm[k]); rm_prev[k] = rm[k]; }

        float h[8];
        #pragma unroll
        for (int k = 0; k < 8; k++) h[k] = fmaxf(er[k], er[k + 1]);

        if (i > 0) {
            #pragma unroll
            for (int k = 0; k < 8; k++) {
                float o = fmaxf(hprev[k], h[k]);  // opened at row rs+i-1
                float d = xbuf[k] - o;
                acc = fmaf(d, d, acc);
            }
        }
        #pragma unroll
        for (int k = 0; k < 8; k++) { hprev[k] = h[k]; xbuf[k] = v[k + 1]; }
    }

    // Finish output row rs+STRIP-1: needs hmax of row rs+STRIP (or bottom clamp).
    if (rs + STRIP < IMG_H) {
        float v[10];
        load_row(base, rs + STRIP, c0, v);
        float rm[9], er[9];
        #pragma unroll
        for (int k = 0; k < 9; k++) rm[k] = fminf(v[k], v[k + 1]);
        if (right_edge) rm[8] = rm[7];
        #pragma unroll
        for (int k = 0; k < 9; k++) er[k] = fminf(rm_prev[k], rm[k]);
        float h[8];
        #pragma unroll
        for (int k = 0; k < 8; k++) h[k] = fmaxf(er[k], er[k + 1]);
        #pragma unroll
        for (int k = 0; k < 8; k++) {
            float o = fmaxf(hprev[k], h[k]);
            float d = xbuf[k] - o;
            acc = fmaf(d, d, acc);
        }
    } else {
        // bottom row: dilation pad duplicates eroded row 511 -> opened = hprev
        #pragma unroll
        for (int k = 0; k < 8; k++) {
            float d = xbuf[k] - hprev[k];
            acc = fmaf(d, d, acc);
        }
    }

    // ---- block reduction (deterministic: fixed tree, no float atomics) ----
    #pragma unroll
    for (int off = 16; off > 0; off >>= 1)
        acc += __shfl_down_sync(0xffffffffu, acc, off);

    __shared__ float  ws[TPB / 32];
    __shared__ int    s_last;
    if ((threadIdx.x & 31) == 0) ws[threadIdx.x >> 5] = acc;
    __syncthreads();
    if (threadIdx.x == 0) {
        float s = 0.f;
        #pragma unroll
        for (int w = 0; w < TPB / 32; w++) s += ws[w];
        g_partials[blockIdx.x] = (double)s;
        __threadfence();
        unsigned tick = atomicAdd(&g_tickets, 1u);
        s_last = (tick == N_BLK - 1);
    }
    __syncthreads();

    // ---- last block: fold 512 partials, deterministic order ----
    if (s_last) {
        __threadfence();  // acquire: make all g_partials writes visible
        double d = g_partials[threadIdx.x] + g_partials[threadIdx.x + TPB];
        #pragma unroll
        for (int off = 16; off > 0; off >>= 1)
            d += __shfl_down_sync(0xffffffffu, d, off);

        __shared__ double wd[TPB / 32];
        if ((threadIdx.x & 31) == 0) wd[threadIdx.x >> 5] = d;
        __syncthreads();
        if (threadIdx.x == 0) {
            double tot = 0.0;
            #pragma unroll
            for (int w = 0; w < TPB / 32; w++) tot += wd[w];
            out[0] = (float)(tot / TOTAL_ELEMS);
            g_tickets = 0;  // reset for next graph replay
        }
    }
}

extern "C" void kernel_launch(void* const* d_in, const int* in_sizes, int n_in,
                              void* d_out, int out_size) {
    (void)in_sizes; (void)n_in; (void)out_size;
    const float* labels = (const float*)d_in[0];
    float* out = (float*)d_out;
    opening_mse_kernel<<<N_BLK, TPB>>>(labels, out);
}

// round 5
// speedup vs baseline: 1.1223x; 1.0453x over previous
#include <cuda_runtime.h>
#include <cuda_bf16.h>

// labels [16, 8, 512, 512] f32 -> scalar f32
//   opened = grey_opening(labels, size=2); out = mean((labels - opened)^2)
// size=2: erosion e[i]=min(x[i-1],x[i]) (clamp at 0); dilation o[i]=max(e[i],e[i+1]) (clamp at H-1).
// Separable. One fused kernel: register-pipelined stencil + MSE + last-block reduction.
// This round: TPB=64 (single balanced wave, 2048 CTAs), software prefetch (row i+1
// loaded before computing row i), incremental row pointers.

#define IMG_H   512
#define IMG_W   512
#define N_IMG   128               // 16 * 8
#define STRIP   32                // output rows per thread
#define TPB     64
#define N_BLK   2048              // 128 imgs * 16 strips * 64 cgroups / 64 tpb
#define TOTAL_ELEMS 33554432.0

__device__ double       g_partials[N_BLK];
__device__ unsigned int g_tickets = 0;   // reset by last block each call -> replay-safe

// Load 10 consecutive columns (c0-1 .. c0+8) at pointer p (= row base + c0),
// float4-aligned. Edge flags select symmetric clamp at image borders.
__device__ __forceinline__ void load_row_p(const float* __restrict__ p,
                                           bool le, bool re, float v[10]) {
    float4 a = __ldg(reinterpret_cast<const float4*>(p));
    float4 b = __ldg(reinterpret_cast<const float4*>(p + 4));
    v[1] = a.x; v[2] = a.y; v[3] = a.z; v[4] = a.w;
    v[5] = b.x; v[6] = b.y; v[7] = b.z; v[8] = b.w;
    v[0] = le ? a.x : __ldg(p - 1);   // erosion left pad: dup col 0
    v[9] = re ? b.w : __ldg(p + 8);   // placeholder at right edge
}

__global__ void __launch_bounds__(TPB, 14)
opening_mse_kernel(const float* __restrict__ x, float* __restrict__ out) {
    const int t     = blockIdx.x * TPB + threadIdx.x;
    const int img   = t >> 10;            // 1024 threads per image
    const int rem   = t & 1023;
    const int strip = rem >> 6;
    const int cg    = rem & 63;
    const int c0    = cg << 3;
    const int rs    = strip * STRIP;
    const bool le   = (c0 == 0);
    const bool re   = (c0 + 8 == IMG_W);
    const bool bot  = (rs + STRIP == IMG_H);

    const float* p = x + (size_t)img * (IMG_H * IMG_W) + rs * IMG_W + c0; // row rs

    // rowmin of row rs-1 (clamped to rs at the top: exactly the erosion top pad).
    float rm_prev[9];
    {
        float v[10];
        load_row_p((rs > 0) ? p - IMG_W : p, le, re, v);
        #pragma unroll
        for (int k = 0; k < 9; k++) rm_prev[k] = fminf(v[k], v[k + 1]);
        if (re) rm_prev[8] = rm_prev[7];  // dilation right pad: dup eroded col 511
    }

    // Prime the pipeline: v0 = row rs.
    float v0[10];
    load_row_p(p, le, re, v0);

    float hprev[8], xbuf[8];
    #pragma unroll
    for (int k = 0; k < 8; k++) { hprev[k] = 0.f; xbuf[k] = 0.f; }
    float acc = 0.f;

    // At iteration i: prefetch row rs+i+1, compute on row rs+i, emit output row rs+i-1.
    #pragma unroll 4
    for (int i = 0; i < STRIP; i++) {
        const bool more = (rs + i + 1 < IMG_H);
        const float* pn = more ? p + IMG_W : p;   // clamp harmless at bottom
        float v1[10];
        load_row_p(pn, le, re, v1);

        float rm[9], er[9];
        #pragma unroll
        for (int k = 0; k < 9; k++) rm[k] = fminf(v0[k], v0[k + 1]);
        if (re) rm[8] = rm[7];
        #pragma unroll
        for (int k = 0; k < 9; k++) { er[k] = fminf(rm_prev[k], rm[k]); rm_prev[k] = rm[k]; }

        float h[8];
        #pragma unroll
        for (int k = 0; k < 8; k++) h[k] = fmaxf(er[k], er[k + 1]);

        if (i > 0) {
            #pragma unroll
            for (int k = 0; k < 8; k++) {
                float o = fmaxf(hprev[k], h[k]);  // opened row rs+i-1
                float d = xbuf[k] - o;
                acc = fmaf(d, d, acc);
            }
        }
        #pragma unroll
        for (int k = 0; k < 8; k++) { hprev[k] = h[k]; xbuf[k] = v0[k + 1]; }
        #pragma unroll
        for (int k = 0; k < 10; k++) v0[k] = v1[k];
        p = pn;
    }

    // Last output row of the strip. For interior strips v0 already holds row
    // rs+STRIP (prefetched). At the bottom, dilation pad gives o[511] = hprev.
    if (!bot) {
        float rm[9], er[9];
        #pragma unroll
        for (int k = 0; k < 9; k++) rm[k] = fminf(v0[k], v0[k + 1]);
        if (re) rm[8] = rm[7];
        #pragma unroll
        for (int k = 0; k < 9; k++) er[k] = fminf(rm_prev[k], rm[k]);
        float h[8];
        #pragma unroll
        for (int k = 0; k < 8; k++) h[k] = fmaxf(er[k], er[k + 1]);
        #pragma unroll
        for (int k = 0; k < 8; k++) {
            float o = fmaxf(hprev[k], h[k]);
            float d = xbuf[k] - o;
            acc = fmaf(d, d, acc);
        }
    } else {
        #pragma unroll
        for (int k = 0; k < 8; k++) {
            float d = xbuf[k] - hprev[k];
            acc = fmaf(d, d, acc);
        }
    }

    // ---- block reduction (deterministic: fixed tree, no float atomics) ----
    #pragma unroll
    for (int off = 16; off > 0; off >>= 1)
        acc += __shfl_down_sync(0xffffffffu, acc, off);

    __shared__ float ws[TPB / 32];
    __shared__ int   s_last;
    if ((threadIdx.x & 31) == 0) ws[threadIdx.x >> 5] = acc;
    __syncthreads();
    if (threadIdx.x == 0) {
        float s = ws[0] + ws[1];
        g_partials[blockIdx.x] = (double)s;
        __threadfence();
        unsigned tick = atomicAdd(&g_tickets, 1u);
        s_last = (tick == N_BLK - 1);
    }
    __syncthreads();

    // ---- last block: fold 2048 partials, deterministic order ----
    if (s_last) {
        __threadfence();  // acquire: make all g_partials writes visible
        double d = 0.0;
        #pragma unroll 4
        for (int j = threadIdx.x; j < N_BLK; j += TPB) d += g_partials[j];
        #pragma unroll
        for (int off = 16; off > 0; off >>= 1)
            d += __shfl_down_sync(0xffffffffu, d, off);

        __shared__ double wd[TPB / 32];
        if ((threadIdx.x & 31) == 0) wd[threadIdx.x >> 5] = d;
        __syncthreads();
        if (threadIdx.x == 0) {
            double tot = wd[0] + wd[1];
            out[0] = (float)(tot / TOTAL_ELEMS);
            g_tickets = 0;  // reset for next graph replay
        }
    }
}

extern "C" void kernel_launch(void* const* d_in, const int* in_sizes, int n_in,
                              void* d_out, int out_size) {
    (void)in_sizes; (void)n_in; (void)out_size;
    const float* labels = (const float*)d_in[0];
    float* out = (float*)d_out;
    opening_mse_kernel<<<N_BLK, TPB>>>(labels, out);
}

// round 6
// speedup vs baseline: 1.1925x; 1.0626x over previous
#include <cuda_runtime.h>
#include <cuda_bf16.h>

// labels [16, 8, 512, 512] f32 -> scalar f32
//   opened = grey_opening(labels, size=2); out = mean((labels - opened)^2)
// size=2: erosion e[i]=min(x[i-1],x[i]) (clamp at 0); dilation o[i]=max(e[i],e[i+1]) (clamp at H-1).
// Separable; register-pipelined down 32-row strips.
// This round: perfectly-coalesced loads. Each warp covers 256 contiguous columns
// as two 4-col groups per thread (A @ C+4*lane, B @ C+128+4*lane); every LDG.128
// is one 512B-contiguous warp transaction (4 L1 wavefronts, no replays).
// Column halos come from __shfl_sync instead of strided scalar LDGs
// (old layout burned ~32 wavefronts/warp-iter -> L1tex-bound at 4.1 TB/s).

#define IMG_H   512
#define IMG_W   512
#define STRIP   32
#define TPB     64
#define N_BLK   2048              // 131072 threads = 128 img * 16 strips * 2 chunks * 32 lanes
#define TOTAL_ELEMS 33554432.0

__device__ double       g_partials[N_BLK];
__device__ unsigned int g_tickets = 0;   // reset by last block each call -> replay-safe

struct RowVals { float4 a, b; float lh, rh; };

// p = rowbase + C + 4*lane (16B aligned). a covers cols [C+4L..C+4L+3],
// b covers [C+128+4L..]. lh/rh are the rare cross-warp halo scalars.
__device__ __forceinline__ RowVals load_rv(const float* __restrict__ p,
                                           bool need_lh, bool need_rh) {
    RowVals r;
    r.a = __ldg(reinterpret_cast<const float4*>(p));
    r.b = __ldg(reinterpret_cast<const float4*>(p + 128));
    r.lh = need_lh ? __ldg(p - 1)   : 0.f;   // col C-1   (lane 0, chunk 1)
    r.rh = need_rh ? __ldg(p + 132) : 0.f;   // col C+256 (lane 31, chunk 0)
    return r;
}

// Horizontal 2-tap min over this row: rm[0..4] for group A, rm[5..9] for group B.
// Halos fetched from adjacent lanes via shfl; image edges use symmetric-pad dup.
__device__ __forceinline__ void rowmin(const RowVals& v, int lane, int chunk,
                                       float rm[10]) {
    const unsigned m = 0xffffffffu;
    float sA3 = __shfl_sync(m, v.a.w, (lane + 31) & 31);  // prev lane a[3]
    float sB3 = __shfl_sync(m, v.b.w, (lane + 31) & 31);  // prev lane b[3]
    float sA0 = __shfl_sync(m, v.a.x, (lane + 1) & 31);   // next lane a[0]
    float sB0 = __shfl_sync(m, v.b.x, (lane + 1) & 31);   // next lane b[0] (wraps: lane31 -> lane0)

    float leftA  = (lane == 0)  ? ((chunk == 0) ? v.a.x : v.lh) : sA3;
    float leftB  = (lane == 0)  ? sA3 : sB3;   // lane0: col C+127 = lane31's a.w
    float rightA = (lane == 31) ? sB0 : sA0;   // lane31: col C+128 = lane0's b.x
    float rightB = (lane == 31) ? v.rh : sB0;  // (chunk1 lane31: garbage, overwritten below)

    rm[0] = fminf(leftA,  v.a.x); rm[1] = fminf(v.a.x, v.a.y);
    rm[2] = fminf(v.a.y, v.a.z);  rm[3] = fminf(v.a.z, v.a.w);
    rm[4] = fminf(v.a.w, rightA);
    rm[5] = fminf(leftB,  v.b.x); rm[6] = fminf(v.b.x, v.b.y);
    rm[7] = fminf(v.b.y, v.b.z);  rm[8] = fminf(v.b.z, v.b.w);
    rm[9] = fminf(v.b.w, rightB);
    if (chunk == 1 && lane == 31) rm[9] = rm[8];  // dilation right pad: dup eroded col 511
}

__global__ void __launch_bounds__(TPB, 14)
opening_mse_kernel(const float* __restrict__ x, float* __restrict__ out) {
    const int t     = blockIdx.x * TPB + threadIdx.x;
    const int lane  = t & 31;
    const int wid_g = t >> 5;            // 4096 warps, 32 per image
    const int img   = wid_g >> 5;
    const int rem   = wid_g & 31;
    const int strip = rem >> 1;
    const int chunk = rem & 1;
    const int C     = chunk << 8;        // 0 or 256
    const int rs    = strip * STRIP;
    const bool bot     = (rs + STRIP == IMG_H);
    const bool need_lh = (lane == 0  && chunk == 1);
    const bool need_rh = (lane == 31 && chunk == 0);

    const float* p = x + (size_t)img * (IMG_H * IMG_W) + rs * IMG_W + C + 4 * lane;

    // rowmin of row rs-1 (clamped to rs at the top == erosion top pad).
    float rm_prev[10];
    {
        RowVals v = load_rv((rs > 0) ? p - IMG_W : p, need_lh, need_rh);
        rowmin(v, lane, chunk, rm_prev);
    }

    // Prime: v0 = row rs.
    RowVals v0 = load_rv(p, need_lh, need_rh);

    float hprev[8], xbuf[8];
    #pragma unroll
    for (int k = 0; k < 8; k++) { hprev[k] = 0.f; xbuf[k] = 0.f; }
    float acc = 0.f;

    // Iter i: prefetch row rs+i+1, compute row rs+i, emit opened row rs+i-1.
    #pragma unroll 4
    for (int i = 0; i < STRIP; i++) {
        const float* pn = (rs + i + 1 < IMG_H) ? p + IMG_W : p;
        RowVals v1 = load_rv(pn, need_lh, need_rh);

        float rm[10], er[10];
        rowmin(v0, lane, chunk, rm);
        #pragma unroll
        for (int k = 0; k < 10; k++) { er[k] = fminf(rm_prev[k], rm[k]); rm_prev[k] = rm[k]; }

        float h[8];
        #pragma unroll
        for (int j = 0; j < 4; j++) {
            h[j]     = fmaxf(er[j],     er[j + 1]);
            h[4 + j] = fmaxf(er[5 + j], er[6 + j]);
        }

        if (i > 0) {
            #pragma unroll
            for (int k = 0; k < 8; k++) {
                float o = fmaxf(hprev[k], h[k]);
                float d = xbuf[k] - o;
                acc = fmaf(d, d, acc);
            }
        }
        #pragma unroll
        for (int k = 0; k < 8; k++) hprev[k] = h[k];
        xbuf[0] = v0.a.x; xbuf[1] = v0.a.y; xbuf[2] = v0.a.z; xbuf[3] = v0.a.w;
        xbuf[4] = v0.b.x; xbuf[5] = v0.b.y; xbuf[6] = v0.b.z; xbuf[7] = v0.b.w;
        v0 = v1;
        p  = pn;
    }

    // Last output row of the strip. Interior: v0 holds prefetched row rs+STRIP.
    // Bottom: dilation pad duplicates eroded row 511 -> opened = hprev.
    if (!bot) {
        float rm[10], er[10];
        rowmin(v0, lane, chunk, rm);
        #pragma unroll
        for (int k = 0; k < 10; k++) er[k] = fminf(rm_prev[k], rm[k]);
        float h[8];
        #pragma unroll
        for (int j = 0; j < 4; j++) {
            h[j]     = fmaxf(er[j],     er[j + 1]);
            h[4 + j] = fmaxf(er[5 + j], er[6 + j]);
        }
        #pragma unroll
        for (int k = 0; k < 8; k++) {
            float o = fmaxf(hprev[k], h[k]);
            float d = xbuf[k] - o;
            acc = fmaf(d, d, acc);
        }
    } else {
        #pragma unroll
        for (int k = 0; k < 8; k++) {
            float d = xbuf[k] - hprev[k];
            acc = fmaf(d, d, acc);
        }
    }

    // ---- block reduction (deterministic: fixed tree, no float atomics) ----
    #pragma unroll
    for (int off = 16; off > 0; off >>= 1)
        acc += __shfl_down_sync(0xffffffffu, acc, off);

    __shared__ float ws[TPB / 32];
    __shared__ int   s_last;
    if ((threadIdx.x & 31) == 0) ws[threadIdx.x >> 5] = acc;
    __syncthreads();
    if (threadIdx.x == 0) {
        float s = ws[0] + ws[1];
        g_partials[blockIdx.x] = (double)s;
        __threadfence();
        unsigned tick = atomicAdd(&g_tickets, 1u);
        s_last = (tick == N_BLK - 1);
    }
    __syncthreads();

    // ---- last block: fold 2048 partials, deterministic order ----
    if (s_last) {
        __threadfence();  // acquire: make all g_partials writes visible
        double d = 0.0;
        #pragma unroll 4
        for (int j = threadIdx.x; j < N_BLK; j += TPB) d += g_partials[j];
        #pragma unroll
        for (int off = 16; off > 0; off >>= 1)
            d += __shfl_down_sync(0xffffffffu, d, off);

        __shared__ double wd[TPB / 32];
        if ((threadIdx.x & 31) == 0) wd[threadIdx.x >> 5] = d;
        __syncthreads();
        if (threadIdx.x == 0) {
            double tot = wd[0] + wd[1];
            out[0] = (float)(tot / TOTAL_ELEMS);
            g_tickets = 0;  // reset for next graph replay
        }
    }
}

extern "C" void kernel_launch(void* const* d_in, const int* in_sizes, int n_in,
                              void* d_out, int out_size) {
    (void)in_sizes; (void)n_in; (void)out_size;
    const float* labels = (const float*)d_in[0];
    float* out = (float*)d_out;
    opening_mse_kernel<<<N_BLK, TPB>>>(labels, out);
}

// round 7
// speedup vs baseline: 1.2695x; 1.0645x over previous
#include <cuda_runtime.h>
#include <cuda_bf16.h>
#include <cuda_pipeline.h>

// labels [16, 8, 512, 512] f32 -> scalar f32
//   opened = grey_opening(labels, size=2); out = mean((labels - opened)^2)
// size=2: erosion e[i]=min(x[i-1],x[i]) (clamp at 0); dilation o[i]=max(e[i],e[i+1]) (clamp at H-1).
// Separable; register-pipelined rowmin/ermin/hmax down 32-row strips.
// This round: per-warp cp.async smem ring (depth 4) so memory-level parallelism is
// decoupled from registers (LDGSTS holds no regs in flight). Consume path reads
// rows from shared (29cyc LDS) instead of global; halos via 2 shfl + 2 one-lane LDS.

#define IMG_H   512
#define IMG_W   512
#define STRIP   32
#define TPB     64
#define N_BLK   2048              // 128 img * 16 strips * 2 chunks(256col) ; 2 warps/CTA
#define D       4                 // ring stages
#define ROWSTR  264               // floats per ring row: 256 data + [256]=right halo + [257]=left halo
#define TOTAL_ELEMS 33554432.0

__device__ double       g_partials[N_BLK];
__device__ unsigned int g_tickets = 0;   // reset by last block each call -> replay-safe

__global__ void __launch_bounds__(TPB, 14)
opening_mse_kernel(const float* __restrict__ x, float* __restrict__ out) {
    __shared__ __align__(16) float ring[2][D][ROWSTR];
    __shared__ float ws[TPB / 32];
    __shared__ int   s_last;

    const int t     = blockIdx.x * TPB + threadIdx.x;
    const int lane  = t & 31;
    const int wcta  = (threadIdx.x >> 5);   // warp in CTA (0/1)
    const int wid_g = t >> 5;               // 4096 warps, 32 per image
    const int img   = wid_g >> 5;
    const int rem   = wid_g & 31;
    const int strip = rem >> 1;
    const int chunk = rem & 1;
    const int C     = chunk << 8;           // 0 or 256
    const int rs    = strip * STRIP;
    const bool bot  = (rs + STRIP == IMG_H);
    const unsigned FULL = 0xffffffffu;

    const float* __restrict__ base = x + (size_t)img * (IMG_H * IMG_W) + C;
    float (* __restrict__ myring)[ROWSTR] = ring[wcta];

    // halo gmem offsets (clamped at image edges; clamp also realizes erosion left pad)
    const int loff = (C > 0) ? -1 : 0;            // col C-1
    const int roff = (C + 256 < IMG_W) ? 256 : 255; // col C+256

    // fetch row for consume-index jp (consume order: jp=0 -> row rs-1, jp -> rs+jp-1)
    auto fetch = [&](int jp) {
        int r = rs + jp - 1;
        r = (r < 0) ? 0 : ((r > IMG_H - 1) ? IMG_H - 1 : r);
        const float* g = base + r * IMG_W;
        float* s = myring[jp & (D - 1)];
        __pipeline_memcpy_async(&s[4 * lane],       &g[4 * lane],       16);
        __pipeline_memcpy_async(&s[4 * lane + 128], &g[4 * lane + 128], 16);
        if (lane < 2) {
            const float* gh = g + ((lane == 0) ? loff : roff);
            float*       sh = &s[(lane == 0) ? 257 : 256];
            __pipeline_memcpy_async(sh, gh, 4);
        }
        __pipeline_commit();
    };

    // prologue: stages 0..D-2 in flight
    fetch(0); fetch(1); fetch(2);

    const int JMAX = STRIP + 1;   // consume jp = 0..33
    auto advance = [&](int jp) {
        __syncwarp();                       // WAR: all lanes done reading recycled stage
        if (jp + D - 1 <= JMAX) fetch(jp + D - 1);
        else __pipeline_commit();           // empty group keeps wait bookkeeping
        __pipeline_wait_prior(D - 1);       // oldest jp+1 groups complete
        __syncwarp();                       // cross-lane visibility of smem fills
    };

    // read 10-wide window for this lane's 8 cols from ring stage jp
    float rm_prev[9], hprev[8], xbuf[8];
    float acc = 0.f;

    auto rowmin_from_stage = [&](int jp, float rm[9], float4& A, float4& B) {
        const float* s = myring[jp & (D - 1)];
        A = *reinterpret_cast<const float4*>(s + 8 * lane);
        B = *reinterpret_cast<const float4*>(s + 8 * lane + 4);
        float v0 = __shfl_up_sync(FULL, B.w, 1);     // prev lane x[c-1]
        float v9 = __shfl_down_sync(FULL, A.x, 1);   // next lane x[c+8]
        if (lane == 0)  v0 = (chunk == 0) ? A.x : s[257];
        if (lane == 31) v9 = s[256];
        rm[0] = fminf(v0,  A.x); rm[1] = fminf(A.x, A.y);
        rm[2] = fminf(A.y, A.z); rm[3] = fminf(A.z, A.w);
        rm[4] = fminf(A.w, B.x); rm[5] = fminf(B.x, B.y);
        rm[6] = fminf(B.y, B.z); rm[7] = fminf(B.z, B.w);
        rm[8] = fminf(B.w, v9);
        if (chunk == 1 && lane == 31) rm[8] = rm[7];  // dilation right pad: rowmin[512]=rowmin[511]
    };

    // jp = 0: rowmin of row rs-1 (clamped -> top erosion pad)
    {
        advance(0);
        float4 A, B;
        rowmin_from_stage(0, rm_prev, A, B);
    }
    #pragma unroll
    for (int k = 0; k < 8; k++) { hprev[k] = 0.f; xbuf[k] = 0.f; }

    // jp = 1..32: row rs+jp-1; emit opened row rs+jp-3 when jp>=2
    #pragma unroll 4
    for (int jp = 1; jp <= STRIP; jp++) {
        advance(jp);
        float rm[9], er[9];
        float4 A, B;
        rowmin_from_stage(jp, rm, A, B);
        #pragma unroll
        for (int k = 0; k < 9; k++) { er[k] = fminf(rm_prev[k], rm[k]); rm_prev[k] = rm[k]; }
        float h[8];
        #pragma unroll
        for (int k = 0; k < 8; k++) h[k] = fmaxf(er[k], er[k + 1]);
        if (jp > 1) {
            #pragma unroll
            for (int k = 0; k < 8; k++) {
                float o = fmaxf(hprev[k], h[k]);
                float d = xbuf[k] - o;
                acc = fmaf(d, d, acc);
            }
        }
        #pragma unroll
        for (int k = 0; k < 8; k++) hprev[k] = h[k];
        xbuf[0] = A.x; xbuf[1] = A.y; xbuf[2] = A.z; xbuf[3] = A.w;
        xbuf[4] = B.x; xbuf[5] = B.y; xbuf[6] = B.z; xbuf[7] = B.w;
    }

    // jp = 33 (row rs+STRIP): finish last output row of the strip.
    {
        advance(JMAX);
        if (!bot) {
            float rm[9], er[9];
            float4 A, B;
            rowmin_from_stage(JMAX, rm, A, B);
            #pragma unroll
            for (int k = 0; k < 9; k++) er[k] = fminf(rm_prev[k], rm[k]);
            float h[8];
            #pragma unroll
            for (int k = 0; k < 8; k++) h[k] = fmaxf(er[k], er[k + 1]);
            #pragma unroll
            for (int k = 0; k < 8; k++) {
                float o = fmaxf(hprev[k], h[k]);
                float d = xbuf[k] - o;
                acc = fmaf(d, d, acc);
            }
        } else {
            // bottom: dilation pad duplicates eroded row 511 -> opened = hprev
            #pragma unroll
            for (int k = 0; k < 8; k++) {
                float d = xbuf[k] - hprev[k];
                acc = fmaf(d, d, acc);
            }
        }
    }

    // ---- block reduction (deterministic: fixed tree, no float atomics) ----
    #pragma unroll
    for (int off = 16; off > 0; off >>= 1)
        acc += __shfl_down_sync(FULL, acc, off);

    if ((threadIdx.x & 31) == 0) ws[threadIdx.x >> 5] = acc;
    __syncthreads();
    if (threadIdx.x == 0) {
        float s = ws[0] + ws[1];
        g_partials[blockIdx.x] = (double)s;
        __threadfence();
        unsigned tick = atomicAdd(&g_tickets, 1u);
        s_last = (tick == N_BLK - 1);
    }
    __syncthreads();

    // ---- last block: fold 2048 partials, deterministic order ----
    if (s_last) {
        __threadfence();  // acquire: make all g_partials writes visible
        double d = 0.0;
        #pragma unroll 4
        for (int j = threadIdx.x; j < N_BLK; j += TPB) d += g_partials[j];
        #pragma unroll
        for (int off = 16; off > 0; off >>= 1)
            d += __shfl_down_sync(FULL, d, off);

        __shared__ double wd[TPB / 32];
        if ((threadIdx.x & 31) == 0) wd[threadIdx.x >> 5] = d;
        __syncthreads();
        if (threadIdx.x == 0) {
            double tot = wd[0] + wd[1];
            out[0] = (float)(tot / TOTAL_ELEMS);
            g_tickets = 0;  // reset for next graph replay
        }
    }
}

extern "C" void kernel_launch(void* const* d_in, const int* in_sizes, int n_in,
                              void* d_out, int out_size) {
    (void)in_sizes; (void)n_in; (void)out_size;
    const float* labels = (const float*)d_in[0];
    float* out = (float*)d_out;
    opening_mse_kernel<<<N_BLK, TPB>>>(labels, out);
}